// round 1
// baseline (speedup 1.0000x reference)
#include <cuda_runtime.h>

// Problem constants
constexpr int B  = 4;
constexpr int S  = 2048;
constexpr int D  = 1024;
constexpr int H  = 16;
constexpr int DK = 64;
constexpr int M_TOTAL = B * S;   // 8192

// Scratch (allocation-free rule: __device__ globals)
// Q/K/V stored head-major: [B, H, S, DK]
__device__ float g_q[B * H * S * DK];
__device__ float g_k[B * H * S * DK];
__device__ float g_v[B * H * S * DK];
// attention context, back in [B, S, D] layout
__device__ float g_ctx[B * S * D];

// ---------------------------------------------------------------------------
// GEMM: Y[m,e] = sum_d A[m,d] * W[e,d] + bias[e]
//   A: [M_TOTAL, D] row-major, W: [D, D] row-major (e-major, matches einsum
//   'bsd,ed->bse'), so both operands are K-major (A @ W^T).
// out_qkv=1: scatter into [B,H,S,DK]; out_qkv=0: plain [m, e].
// Tiling: 128x128x8, 256 threads, 8x8 microtile.
// ---------------------------------------------------------------------------
constexpr int BM = 128, BN = 128, BK = 8;

__global__ __launch_bounds__(256)
void gemm_kernel(const float* __restrict__ A, const float* __restrict__ W,
                 const float* __restrict__ bias, float* __restrict__ Y,
                 int out_qkv)
{
    __shared__ float As[BK][BM + 4];
    __shared__ float Bs[BK][BN + 4];

    const int tid = threadIdx.x;
    const int m0 = blockIdx.y * BM;
    const int n0 = blockIdx.x * BN;
    const int tx = tid & 15;        // 0..15 -> n
    const int ty = tid >> 4;        // 0..15 -> m

    float acc[8][8];
#pragma unroll
    for (int i = 0; i < 8; i++)
#pragma unroll
        for (int j = 0; j < 8; j++) acc[i][j] = 0.f;

    // cooperative load mapping: 256 threads -> 128 rows x 2 float4 cols
    const int lr = tid >> 1;            // 0..127 tile row
    const int lc = (tid & 1) * 4;       // 0 or 4 (k offset)

    for (int k0 = 0; k0 < D; k0 += BK) {
        float4 av = *(const float4*)&A[(m0 + lr) * D + k0 + lc];
        float4 bv = *(const float4*)&W[(n0 + lr) * D + k0 + lc];
        As[lc + 0][lr] = av.x; As[lc + 1][lr] = av.y;
        As[lc + 2][lr] = av.z; As[lc + 3][lr] = av.w;
        Bs[lc + 0][lr] = bv.x; Bs[lc + 1][lr] = bv.y;
        Bs[lc + 2][lr] = bv.z; Bs[lc + 3][lr] = bv.w;
        __syncthreads();

#pragma unroll
        for (int k = 0; k < BK; k++) {
            float a[8], b[8];
#pragma unroll
            for (int i = 0; i < 8; i++) a[i] = As[k][ty * 8 + i];
#pragma unroll
            for (int j = 0; j < 8; j++) b[j] = Bs[k][tx * 8 + j];
#pragma unroll
            for (int i = 0; i < 8; i++)
#pragma unroll
                for (int j = 0; j < 8; j++) acc[i][j] += a[i] * b[j];
        }
        __syncthreads();
    }

    // epilogue
#pragma unroll
    for (int i = 0; i < 8; i++) {
        const int m = m0 + ty * 8 + i;
#pragma unroll
        for (int j = 0; j < 8; j++) {
            const int e = n0 + tx * 8 + j;
            const float v = acc[i][j] + bias[e];
            if (out_qkv) {
                const int bb = m >> 11;        // m / S
                const int s  = m & (S - 1);    // m % S
                const int h  = e >> 6;         // e / DK
                const int dk = e & (DK - 1);   // e % DK
                Y[(((bb * H) + h) * S + s) * DK + dk] = v;
            } else {
                Y[m * D + e] = v;
            }
        }
    }
}

// ---------------------------------------------------------------------------
// Flash-style masked attention, fp32.
// Thread-per-query-row: softmax state lives entirely in registers; no
// cross-thread reduction. K/V tiles of 32 keys staged in smem (broadcast
// reads: all 128 threads read the same address -> conflict-free).
// grid = (S/128, H, B), block = 128 threads.
// ---------------------------------------------------------------------------
constexpr int TQ = 128;
constexpr int TK = 32;

__global__ __launch_bounds__(128)
void attn_kernel(const int* __restrict__ mask, float* __restrict__ ctx)
{
    __shared__ float Ks[TK * DK];   // 8 KB
    __shared__ float Vs[TK * DK];   // 8 KB

    const int tid = threadIdx.x;
    const int b = blockIdx.z;
    const int h = blockIdx.y;
    const int q = blockIdx.x * TQ + tid;

    const float* qptr  = g_q + (((b * H) + h) * S + q) * DK;
    const float* kbase = g_k + (((b * H) + h) * S) * DK;
    const float* vbase = g_v + (((b * H) + h) * S) * DK;
    const int*   mrow  = mask + (b * S + q) * S;

    // pre-scale q by 1/sqrt(DK) so scores come out scaled
    float qr[DK];
    const float scale = 0.125f;
#pragma unroll
    for (int d = 0; d < DK; d += 4) {
        float4 t = *(const float4*)&qptr[d];
        qr[d + 0] = t.x * scale; qr[d + 1] = t.y * scale;
        qr[d + 2] = t.z * scale; qr[d + 3] = t.w * scale;
    }

    float o[DK];
#pragma unroll
    for (int d = 0; d < DK; d++) o[d] = 0.f;
    float mrun = -1e30f, lrun = 0.f;

    for (int kt = 0; kt < S; kt += TK) {
        // cooperative tile load: 2048 floats each, 4x float4 per thread
        const float4* ksrc = (const float4*)(kbase + kt * DK);
        const float4* vsrc = (const float4*)(vbase + kt * DK);
        float4* kd = (float4*)Ks;
        float4* vd = (float4*)Vs;
#pragma unroll
        for (int r = 0; r < 4; r++) {
            kd[r * 128 + tid] = ksrc[r * 128 + tid];
            vd[r * 128 + tid] = vsrc[r * 128 + tid];
        }
        __syncthreads();

        // scores for this tile
        float sv[TK];
#pragma unroll 4
        for (int j = 0; j < TK; j++) {
            const float4* kr = (const float4*)&Ks[j * DK];
            float s0 = 0.f, s1 = 0.f;
#pragma unroll
            for (int d4 = 0; d4 < 16; d4 += 2) {
                float4 ka = kr[d4];
                float4 kb = kr[d4 + 1];
                s0 += qr[d4 * 4 + 0] * ka.x + qr[d4 * 4 + 1] * ka.y
                    + qr[d4 * 4 + 2] * ka.z + qr[d4 * 4 + 3] * ka.w;
                s1 += qr[d4 * 4 + 4] * kb.x + qr[d4 * 4 + 5] * kb.y
                    + qr[d4 * 4 + 6] * kb.z + qr[d4 * 4 + 7] * kb.w;
            }
            sv[j] = s0 + s1;
        }

        // mask: 0 -> -1e9 (exactly matches reference semantics)
#pragma unroll
        for (int j = 0; j < TK; j += 4) {
            int4 mm = *(const int4*)&mrow[kt + j];
            if (mm.x == 0) sv[j + 0] = -1e9f;
            if (mm.y == 0) sv[j + 1] = -1e9f;
            if (mm.z == 0) sv[j + 2] = -1e9f;
            if (mm.w == 0) sv[j + 3] = -1e9f;
        }

        // online softmax update
        float mt = mrun;
#pragma unroll
        for (int j = 0; j < TK; j++) mt = fmaxf(mt, sv[j]);
        const float corr = __expf(mrun - mt);
        lrun *= corr;
#pragma unroll
        for (int d = 0; d < DK; d++) o[d] *= corr;

#pragma unroll 4
        for (int j = 0; j < TK; j++) {
            const float p = __expf(sv[j] - mt);
            lrun += p;
            const float4* vr = (const float4*)&Vs[j * DK];
#pragma unroll
            for (int d4 = 0; d4 < 16; d4++) {
                float4 vv = vr[d4];
                o[d4 * 4 + 0] += p * vv.x;
                o[d4 * 4 + 1] += p * vv.y;
                o[d4 * 4 + 2] += p * vv.z;
                o[d4 * 4 + 3] += p * vv.w;
            }
        }
        mrun = mt;
        __syncthreads();
    }

    const float inv = 1.f / lrun;
    float* optr = ctx + (b * S + q) * D + h * DK;
#pragma unroll
    for (int d4 = 0; d4 < 16; d4++) {
        float4 w;
        w.x = o[d4 * 4 + 0] * inv;
        w.y = o[d4 * 4 + 1] * inv;
        w.z = o[d4 * 4 + 2] * inv;
        w.w = o[d4 * 4 + 3] * inv;
        *(float4*)&optr[d4 * 4] = w;
    }
}

// ---------------------------------------------------------------------------
// launch
// ---------------------------------------------------------------------------
extern "C" void kernel_launch(void* const* d_in, const int* in_sizes, int n_in,
                              void* d_out, int out_size)
{
    const float* query = (const float*)d_in[0];
    const float* key_  = (const float*)d_in[1];
    const float* value = (const float*)d_in[2];
    const int*   amask = (const int*)  d_in[3];
    const float* w_q = (const float*)d_in[4];
    const float* b_q = (const float*)d_in[5];
    const float* w_k = (const float*)d_in[6];
    const float* b_k = (const float*)d_in[7];
    const float* w_v = (const float*)d_in[8];
    const float* b_v = (const float*)d_in[9];
    const float* w_o = (const float*)d_in[10];
    const float* b_o = (const float*)d_in[11];
    float* out = (float*)d_out;

    float *gq, *gk, *gv, *gctx;
    cudaGetSymbolAddress((void**)&gq,   g_q);
    cudaGetSymbolAddress((void**)&gk,   g_k);
    cudaGetSymbolAddress((void**)&gv,   g_v);
    cudaGetSymbolAddress((void**)&gctx, g_ctx);

    const dim3 gemm_grid(D / BN, M_TOTAL / BM);   // (8, 64)
    const dim3 gemm_block(256);

    // QKV projections -> head-major [B,H,S,DK]
    gemm_kernel<<<gemm_grid, gemm_block>>>(query, w_q, b_q, gq, 1);
    gemm_kernel<<<gemm_grid, gemm_block>>>(key_,  w_k, b_k, gk, 1);
    gemm_kernel<<<gemm_grid, gemm_block>>>(value, w_v, b_v, gv, 1);

    // masked flash attention -> [B,S,D]
    const dim3 attn_grid(S / TQ, H, B);           // (16, 16, 4)
    attn_kernel<<<attn_grid, 128>>>(amask, gctx);

    // output projection -> d_out [B,S,D]
    gemm_kernel<<<gemm_grid, gemm_block>>>(gctx, w_o, b_o, out, 0);
}

// round 3
// speedup vs baseline: 1.2998x; 1.2998x over previous
#include <cuda_runtime.h>
#include <cuda_bf16.h>
#include <cstdint>

// Problem constants
constexpr int B  = 4;
constexpr int S  = 2048;
constexpr int D  = 1024;
constexpr int H  = 16;
constexpr int DK = 64;
constexpr int M_TOTAL = B * S;   // 8192

// hi/lo split layouts: A' [M, 2D] = [a_hi | a_lo], W' [N, 2D] = [w_hi | w_lo]
constexpr int KA = 2 * D;        // 2048

// ---------------------------------------------------------------------------
// Device scratch (allocation-free rule)
// ---------------------------------------------------------------------------
__device__ __nv_bfloat16 g_ab[(size_t)M_TOTAL * KA];  // 32 MB
__device__ __nv_bfloat16 g_wb[(size_t)D * KA];        // 4 MB
__device__ float g_q[(size_t)B * H * S * DK];
__device__ float g_k[(size_t)B * H * S * DK];
__device__ float g_v[(size_t)B * H * S * DK];
__device__ float g_ctx[(size_t)B * S * D];

// ---------------------------------------------------------------------------
// helpers
// ---------------------------------------------------------------------------
__device__ __forceinline__ uint32_t smem_u32(const void* p) {
    uint32_t a;
    asm("{ .reg .u64 t; cvta.to.shared.u64 t, %1; cvt.u32.u64 %0, t; }"
        : "=r"(a) : "l"(p));
    return a;
}
__device__ __forceinline__ void cp16(uint32_t s, const void* g) {
    asm volatile("cp.async.cg.shared.global [%0], [%1], 16;" :: "r"(s), "l"(g));
}
__device__ __forceinline__ void ldmatrix_x4(uint32_t& r0, uint32_t& r1,
                                            uint32_t& r2, uint32_t& r3, uint32_t a) {
    asm volatile("ldmatrix.sync.aligned.m8n8.x4.shared.b16 {%0,%1,%2,%3}, [%4];"
                 : "=r"(r0), "=r"(r1), "=r"(r2), "=r"(r3) : "r"(a));
}
__device__ __forceinline__ void ldmatrix_x2(uint32_t& r0, uint32_t& r1, uint32_t a) {
    asm volatile("ldmatrix.sync.aligned.m8n8.x2.shared.b16 {%0,%1}, [%2];"
                 : "=r"(r0), "=r"(r1) : "r"(a));
}
__device__ __forceinline__ void mma_bf16(float* c, const uint32_t* a, const uint32_t* b) {
    asm volatile("mma.sync.aligned.m16n8k16.row.col.f32.bf16.bf16.f32 "
                 "{%0,%1,%2,%3},{%4,%5,%6,%7},{%8,%9},{%0,%1,%2,%3};"
                 : "+f"(c[0]), "+f"(c[1]), "+f"(c[2]), "+f"(c[3])
                 : "r"(a[0]), "r"(a[1]), "r"(a[2]), "r"(a[3]), "r"(b[0]), "r"(b[1]));
}

// packed f32x2 (sm_100 family feature — not 'a'-gated)
__device__ __forceinline__ unsigned long long pack2(float x, float y) {
    unsigned long long r;
    asm("mov.b64 %0, {%1,%2};" : "=l"(r) : "f"(x), "f"(y));
    return r;
}
__device__ __forceinline__ void unpack2(unsigned long long v, float& x, float& y) {
    asm("mov.b64 {%0,%1}, %2;" : "=f"(x), "=f"(y) : "l"(v));
}
__device__ __forceinline__ void fma2(unsigned long long& d,
                                     unsigned long long a, unsigned long long b) {
    asm("fma.rn.f32x2 %0, %1, %2, %0;" : "+l"(d) : "l"(a), "l"(b));
}
__device__ __forceinline__ void mul2(unsigned long long& d, unsigned long long b) {
    asm("mul.rn.f32x2 %0, %1, %2;" : "=l"(d) : "l"(d), "l"(b));
}

// ---------------------------------------------------------------------------
// Conversion kernels: fp32 -> bf16 hi/lo
// ---------------------------------------------------------------------------
__global__ __launch_bounds__(256)
void conv_act(const float* __restrict__ X, __nv_bfloat16* __restrict__ Yb)
{
    const int i = (blockIdx.x * 256 + threadIdx.x) * 4;
    float4 x = *(const float4*)(X + i);
    const int row = i >> 10;
    const int col = i & (D - 1);
    float xv[4] = {x.x, x.y, x.z, x.w};
    __nv_bfloat162 hv[2], lv[2];
#pragma unroll
    for (int j = 0; j < 2; j++) {
        __nv_bfloat16 h0 = __float2bfloat16(xv[2*j]);
        __nv_bfloat16 h1 = __float2bfloat16(xv[2*j+1]);
        hv[j] = __nv_bfloat162(h0, h1);
        lv[j] = __nv_bfloat162(__float2bfloat16(xv[2*j]   - __bfloat162float(h0)),
                               __float2bfloat16(xv[2*j+1] - __bfloat162float(h1)));
    }
    __nv_bfloat162* ph = (__nv_bfloat162*)(Yb + (size_t)row * KA + col);
    __nv_bfloat162* pl = (__nv_bfloat162*)(Yb + (size_t)row * KA + D + col);
    ph[0] = hv[0]; ph[1] = hv[1];
    pl[0] = lv[0]; pl[1] = lv[1];
}

// ---------------------------------------------------------------------------
// bf16 mma.sync GEMM with hi/lo split (3 products):
//   Y[m,e] = sum_k A[m,k] W[e,k] + bias[e]
// block tile 128x128, K-chunk 32 (per half), 8 warps (64x32 each),
// 2-stage cp.async pipeline, 8x8-block smem layout (conflict-free ldmatrix).
// ---------------------------------------------------------------------------
constexpr int BKC = 32;
constexpr int NCH = D / BKC;               // 32 chunks
constexpr int TILE_B  = 128 * BKC * 2;     // 8192 B per sub-tile
constexpr int STAGE_B = 4 * TILE_B;        // Ahi, Alo, Whi, Wlo = 32 KB
constexpr int GEMM_SMEM = 2 * STAGE_B;     // 64 KB

__global__ __launch_bounds__(256)
void gemm_tc(const __nv_bfloat16* __restrict__ Ab, const __nv_bfloat16* __restrict__ Wb,
             const float* __restrict__ bias, float* __restrict__ Y, int out_qkv)
{
    extern __shared__ char smem[];
    const uint32_t sbase = smem_u32(smem);
    const int tid  = threadIdx.x;
    const int wid  = tid >> 5;
    const int lane = tid & 31;
    const int m0 = blockIdx.y * 128;
    const int n0 = blockIdx.x * 128;
    const int wm = (wid >> 2) * 64;        // 0 or 64
    const int wn = (wid & 3) * 32;         // 0,32,64,96

    float acc[4][4][4];
#pragma unroll
    for (int mi = 0; mi < 4; mi++)
#pragma unroll
        for (int ni = 0; ni < 4; ni++)
#pragma unroll
            for (int r = 0; r < 4; r++) acc[mi][ni][r] = 0.f;

    // cooperative load mapping: thread t -> row t>>1, k-halves (t&1)
    const int lr = tid >> 1;
    const int lh = tid & 1;

    auto load_chunk = [&](int c) {
        const uint32_t stage = sbase + (uint32_t)(c & 1) * STAGE_B;
        const int kc = c * BKC;
        const int mg = lr >> 3, r8 = lr & 7;
        const __nv_bfloat16* ga = Ab + (size_t)(m0 + lr) * KA + kc;
        const __nv_bfloat16* gw = Wb + (size_t)(n0 + lr) * KA + kc;
#pragma unroll
        for (int j = 0; j < 2; j++) {
            const int kg = lh * 2 + j;     // 0..3 (8-elem group)
            const uint32_t so = (uint32_t)((kg * 16 + mg) * 128 + r8 * 16);
            cp16(stage + 0 * TILE_B + so, ga + kg * 8);          // A hi
            cp16(stage + 1 * TILE_B + so, ga + D + kg * 8);      // A lo
            cp16(stage + 2 * TILE_B + so, gw + kg * 8);          // W hi
            cp16(stage + 3 * TILE_B + so, gw + D + kg * 8);      // W lo
        }
        asm volatile("cp.async.commit_group;");
    };

    load_chunk(0);
    load_chunk(1);

    // per-lane ldmatrix address components
    const int gA  = lane >> 3;             // 0..3
    const int rA  = lane & 7;
    const int la  = lane & 15;
    const int gB  = la >> 3;               // 0..1
    const int rB  = la & 7;

    for (int c = 0; c < NCH; c++) {
        if (c + 1 < NCH) asm volatile("cp.async.wait_group 1;" ::: "memory");
        else             asm volatile("cp.async.wait_group 0;" ::: "memory");
        __syncthreads();

        const uint32_t stage = sbase + (uint32_t)(c & 1) * STAGE_B;
        const uint32_t ahiB = stage;
        const uint32_t aloB = stage + TILE_B;
        const uint32_t whiB = stage + 2 * TILE_B;
        const uint32_t wloB = stage + 3 * TILE_B;

#pragma unroll
        for (int ks = 0; ks < 2; ks++) {
            const int kg0 = ks * 2;
            uint32_t ahi[4][4], alo[4][4], bhi[4][2], blo[4][2];
#pragma unroll
            for (int mi = 0; mi < 4; mi++) {
                const int mgB = (wm >> 3) + mi * 2 + (gA & 1);
                const int kgB = kg0 + (gA >> 1);
                const uint32_t off = (uint32_t)((kgB * 16 + mgB) * 128 + rA * 16);
                ldmatrix_x4(ahi[mi][0], ahi[mi][1], ahi[mi][2], ahi[mi][3], ahiB + off);
                ldmatrix_x4(alo[mi][0], alo[mi][1], alo[mi][2], alo[mi][3], aloB + off);
            }
#pragma unroll
            for (int ni = 0; ni < 4; ni++) {
                const int ng  = (wn >> 3) + ni;
                const int kgB = kg0 + gB;
                const uint32_t off = (uint32_t)((kgB * 16 + ng) * 128 + rB * 16);
                ldmatrix_x2(bhi[ni][0], bhi[ni][1], whiB + off);
                ldmatrix_x2(blo[ni][0], blo[ni][1], wloB + off);
            }
#pragma unroll
            for (int mi = 0; mi < 4; mi++)
#pragma unroll
                for (int ni = 0; ni < 4; ni++) {
                    mma_bf16(acc[mi][ni], ahi[mi], bhi[ni]);
                    mma_bf16(acc[mi][ni], ahi[mi], blo[ni]);
                    mma_bf16(acc[mi][ni], alo[mi], bhi[ni]);
                }
        }
        __syncthreads();
        if (c + 2 < NCH) load_chunk(c + 2);
    }

    // epilogue: bias + (optional) head-major scatter
#pragma unroll
    for (int mi = 0; mi < 4; mi++) {
#pragma unroll
        for (int ni = 0; ni < 4; ni++) {
            const int m = m0 + wm + mi * 16 + (lane >> 2);
            const int n = n0 + wn + ni * 8 + (lane & 3) * 2;
            const float b0 = __ldg(&bias[n]);
            const float b1 = __ldg(&bias[n + 1]);
            float2 v0 = make_float2(acc[mi][ni][0] + b0, acc[mi][ni][1] + b1);
            float2 v1 = make_float2(acc[mi][ni][2] + b0, acc[mi][ni][3] + b1);
            if (out_qkv) {
                const int h  = n >> 6;
                const int dk = n & (DK - 1);
                const int bb = m >> 11;
                const int s  = m & (S - 1);
                float* base = Y + ((((size_t)bb * H + h) * S + s) * DK + dk);
                *(float2*)base = v0;
                const int s2 = (m + 8) & (S - 1);
                const int b2 = (m + 8) >> 11;
                float* base2 = Y + ((((size_t)b2 * H + h) * S + s2) * DK + dk);
                *(float2*)base2 = v1;
            } else {
                *(float2*)(Y + (size_t)m * D + n)       = v0;
                *(float2*)(Y + (size_t)(m + 8) * D + n) = v1;
            }
        }
    }
}

// ---------------------------------------------------------------------------
// Flash-style masked attention, packed f32x2 math.
// Thread-per-query-row; K/V tiles of 32 keys in smem.
// ---------------------------------------------------------------------------
constexpr int TQ = 128;
constexpr int TK = 32;

__global__ __launch_bounds__(128)
void attn_kernel(const int* __restrict__ mask, float* __restrict__ ctx)
{
    __shared__ float Ks[TK * DK];
    __shared__ float Vs[TK * DK];

    const int tid = threadIdx.x;
    const int b = blockIdx.z;
    const int h = blockIdx.y;
    const int q = blockIdx.x * TQ + tid;

    const float* qptr  = g_q + (((size_t)(b * H) + h) * S + q) * DK;
    const float* kbase = g_k + (((size_t)(b * H) + h) * S) * DK;
    const float* vbase = g_v + (((size_t)(b * H) + h) * S) * DK;
    const int*   mrow  = mask + ((size_t)b * S + q) * S;

    // q pre-scaled, packed into 32 f32x2 regs
    unsigned long long qr2[DK / 2];
    const float scale = 0.125f;
#pragma unroll
    for (int d = 0; d < DK; d += 4) {
        float4 t = *(const float4*)&qptr[d];
        qr2[d / 2]     = pack2(t.x * scale, t.y * scale);
        qr2[d / 2 + 1] = pack2(t.z * scale, t.w * scale);
    }

    unsigned long long o2[DK / 2];
#pragma unroll
    for (int i = 0; i < DK / 2; i++) o2[i] = 0ull;
    float mrun = -1e30f, lrun = 0.f;

    for (int kt = 0; kt < S; kt += TK) {
        const float4* ksrc = (const float4*)(kbase + (size_t)kt * DK);
        const float4* vsrc = (const float4*)(vbase + (size_t)kt * DK);
        float4* kd = (float4*)Ks;
        float4* vd = (float4*)Vs;
#pragma unroll
        for (int r = 0; r < 4; r++) {
            kd[r * 128 + tid] = ksrc[r * 128 + tid];
            vd[r * 128 + tid] = vsrc[r * 128 + tid];
        }
        __syncthreads();

        float sv[TK];
#pragma unroll 4
        for (int j = 0; j < TK; j++) {
            const ulonglong2* kr = (const ulonglong2*)&Ks[j * DK];
            unsigned long long s2a = 0ull, s2b = 0ull;
#pragma unroll
            for (int d = 0; d < 16; d++) {
                ulonglong2 k2 = kr[d];
                fma2(s2a, qr2[2 * d],     k2.x);
                fma2(s2b, qr2[2 * d + 1], k2.y);
            }
            float xa, ya, xb, yb;
            unpack2(s2a, xa, ya);
            unpack2(s2b, xb, yb);
            sv[j] = (xa + xb) + (ya + yb);
        }

#pragma unroll
        for (int j = 0; j < TK; j += 4) {
            int4 mm = *(const int4*)&mrow[kt + j];
            if (mm.x == 0) sv[j + 0] = -1e9f;
            if (mm.y == 0) sv[j + 1] = -1e9f;
            if (mm.z == 0) sv[j + 2] = -1e9f;
            if (mm.w == 0) sv[j + 3] = -1e9f;
        }

        float mt = mrun;
#pragma unroll
        for (int j = 0; j < TK; j++) mt = fmaxf(mt, sv[j]);
        const float corr = __expf(mrun - mt);
        lrun *= corr;
        const unsigned long long c2 = pack2(corr, corr);
#pragma unroll
        for (int i = 0; i < DK / 2; i++) mul2(o2[i], c2);

#pragma unroll 4
        for (int j = 0; j < TK; j++) {
            const float p = __expf(sv[j] - mt);
            lrun += p;
            const unsigned long long pk = pack2(p, p);
            const ulonglong2* vr = (const ulonglong2*)&Vs[j * DK];
#pragma unroll
            for (int d = 0; d < 16; d++) {
                ulonglong2 v2 = vr[d];
                fma2(o2[2 * d],     pk, v2.x);
                fma2(o2[2 * d + 1], pk, v2.y);
            }
        }
        mrun = mt;
        __syncthreads();
    }

    const float inv = 1.f / lrun;
    float* optr = ctx + ((size_t)b * S + q) * D + h * DK;
#pragma unroll
    for (int i = 0; i < DK / 2; i += 2) {
        float x0, y0, x1, y1;
        unpack2(o2[i], x0, y0);
        unpack2(o2[i + 1], x1, y1);
        float4 w = make_float4(x0 * inv, y0 * inv, x1 * inv, y1 * inv);
        *(float4*)&optr[i * 2] = w;
    }
}

// ---------------------------------------------------------------------------
// launch
// ---------------------------------------------------------------------------
extern "C" void kernel_launch(void* const* d_in, const int* in_sizes, int n_in,
                              void* d_out, int out_size)
{
    const float* query = (const float*)d_in[0];
    const float* key_  = (const float*)d_in[1];
    const float* value = (const float*)d_in[2];
    const int*   amask = (const int*)  d_in[3];
    const float* w_q = (const float*)d_in[4];
    const float* b_q = (const float*)d_in[5];
    const float* w_k = (const float*)d_in[6];
    const float* b_k = (const float*)d_in[7];
    const float* w_v = (const float*)d_in[8];
    const float* b_v = (const float*)d_in[9];
    const float* w_o = (const float*)d_in[10];
    const float* b_o = (const float*)d_in[11];
    float* out = (float*)d_out;

    __nv_bfloat16 *gab, *gwb;
    float *gq, *gk, *gv, *gctx;
    cudaGetSymbolAddress((void**)&gab,  g_ab);
    cudaGetSymbolAddress((void**)&gwb,  g_wb);
    cudaGetSymbolAddress((void**)&gq,   g_q);
    cudaGetSymbolAddress((void**)&gk,   g_k);
    cudaGetSymbolAddress((void**)&gv,   g_v);
    cudaGetSymbolAddress((void**)&gctx, g_ctx);

    cudaFuncSetAttribute(gemm_tc, cudaFuncAttributeMaxDynamicSharedMemorySize, GEMM_SMEM);

    const dim3 gg(D / 128, M_TOTAL / 128);                // (8, 64)
    const int conv_act_blocks = M_TOTAL * D / (4 * 256);  // 8192
    const int conv_w_blocks   = D * D / (4 * 256);        // 1024

    conv_act<<<conv_act_blocks, 256>>>(query, gab);
    conv_act<<<conv_w_blocks, 256>>>(w_q, gwb);           // same layout transform works for W
    gemm_tc<<<gg, 256, GEMM_SMEM>>>(gab, gwb, b_q, gq, 1);

    conv_act<<<conv_act_blocks, 256>>>(key_, gab);
    conv_act<<<conv_w_blocks, 256>>>(w_k, gwb);
    gemm_tc<<<gg, 256, GEMM_SMEM>>>(gab, gwb, b_k, gk, 1);

    conv_act<<<conv_act_blocks, 256>>>(value, gab);
    conv_act<<<conv_w_blocks, 256>>>(w_v, gwb);
    gemm_tc<<<gg, 256, GEMM_SMEM>>>(gab, gwb, b_v, gv, 1);

    const dim3 attn_grid(S / TQ, H, B);                   // (16, 16, 4)
    attn_kernel<<<attn_grid, 128>>>(amask, gctx);

    conv_act<<<conv_act_blocks, 256>>>(gctx, gab);
    conv_act<<<conv_w_blocks, 256>>>(w_o, gwb);
    gemm_tc<<<gg, 256, GEMM_SMEM>>>(gab, gwb, b_o, out, 0);
}

// round 5
// speedup vs baseline: 2.5167x; 1.9361x over previous
#include <cuda_runtime.h>
#include <cuda_bf16.h>
#include <cstdint>

// Problem constants
constexpr int B  = 4;
constexpr int S  = 2048;
constexpr int D  = 1024;
constexpr int H  = 16;
constexpr int DK = 64;
constexpr int M_TOTAL = B * S;   // 8192

// hi/lo split layouts: A' [M, 2D] = [a_hi | a_lo], W' [N, 2D] = [w_hi | w_lo]
constexpr int KA = 2 * D;        // 2048

// ---------------------------------------------------------------------------
// Device scratch (allocation-free rule)
// ---------------------------------------------------------------------------
__device__ __nv_bfloat16 g_ab[(size_t)M_TOTAL * KA];        // 32 MB
__device__ __nv_bfloat16 g_wb[(size_t)D * KA];              // 4 MB
// Q/K/V head-major bf16 hi/lo rows: [B,H,S,128]  (dk 0..63 = hi, 64..127 = lo)
__device__ __nv_bfloat16 g_qb[(size_t)B * H * S * 128];     // 32 MB
__device__ __nv_bfloat16 g_kb[(size_t)B * H * S * 128];
__device__ __nv_bfloat16 g_vb[(size_t)B * H * S * 128];
__device__ float g_ctx[(size_t)B * S * D];                  // 32 MB

// ---------------------------------------------------------------------------
// helpers
// ---------------------------------------------------------------------------
__device__ __forceinline__ uint32_t smem_u32(const void* p) {
    uint32_t a;
    asm("{ .reg .u64 t; cvta.to.shared.u64 t, %1; cvt.u32.u64 %0, t; }"
        : "=r"(a) : "l"(p));
    return a;
}
__device__ __forceinline__ void cp16(uint32_t s, const void* g) {
    asm volatile("cp.async.cg.shared.global [%0], [%1], 16;" :: "r"(s), "l"(g));
}
__device__ __forceinline__ void ldmatrix_x4(uint32_t& r0, uint32_t& r1,
                                            uint32_t& r2, uint32_t& r3, uint32_t a) {
    asm volatile("ldmatrix.sync.aligned.m8n8.x4.shared.b16 {%0,%1,%2,%3}, [%4];"
                 : "=r"(r0), "=r"(r1), "=r"(r2), "=r"(r3) : "r"(a));
}
__device__ __forceinline__ void ldmatrix_x4_t(uint32_t& r0, uint32_t& r1,
                                              uint32_t& r2, uint32_t& r3, uint32_t a) {
    asm volatile("ldmatrix.sync.aligned.m8n8.x4.trans.shared.b16 {%0,%1,%2,%3}, [%4];"
                 : "=r"(r0), "=r"(r1), "=r"(r2), "=r"(r3) : "r"(a));
}
__device__ __forceinline__ void ldmatrix_x2(uint32_t& r0, uint32_t& r1, uint32_t a) {
    asm volatile("ldmatrix.sync.aligned.m8n8.x2.shared.b16 {%0,%1}, [%2];"
                 : "=r"(r0), "=r"(r1) : "r"(a));
}
__device__ __forceinline__ void mma_bf16(float* c, const uint32_t* a, const uint32_t* b) {
    asm volatile("mma.sync.aligned.m16n8k16.row.col.f32.bf16.bf16.f32 "
                 "{%0,%1,%2,%3},{%4,%5,%6,%7},{%8,%9},{%0,%1,%2,%3};"
                 : "+f"(c[0]), "+f"(c[1]), "+f"(c[2]), "+f"(c[3])
                 : "r"(a[0]), "r"(a[1]), "r"(a[2]), "r"(a[3]), "r"(b[0]), "r"(b[1]));
}
// pack two f32 into bf16x2: low half = plo, high half = phi
__device__ __forceinline__ uint32_t cvt2bf(float phi, float plo) {
    uint32_t r;
    asm("cvt.rn.bf16x2.f32 %0, %1, %2;" : "=r"(r) : "f"(phi), "f"(plo));
    return r;
}
__device__ __forceinline__ float bf_lo(uint32_t p) { return __uint_as_float(p << 16); }
__device__ __forceinline__ float bf_hi(uint32_t p) { return __uint_as_float(p & 0xFFFF0000u); }

// ---------------------------------------------------------------------------
// Conversion kernel: fp32 [R, D] -> bf16 hi/lo [R, 2D]
// ---------------------------------------------------------------------------
__global__ __launch_bounds__(256)
void conv_act(const float* __restrict__ X, __nv_bfloat16* __restrict__ Yb)
{
    const int i = (blockIdx.x * 256 + threadIdx.x) * 4;
    float4 x = *(const float4*)(X + i);
    const int row = i >> 10;
    const int col = i & (D - 1);
    float xv[4] = {x.x, x.y, x.z, x.w};
    uint32_t hp[2], lp[2];
#pragma unroll
    for (int j = 0; j < 2; j++) {
        hp[j] = cvt2bf(xv[2*j+1], xv[2*j]);
        lp[j] = cvt2bf(xv[2*j+1] - bf_hi(hp[j]), xv[2*j] - bf_lo(hp[j]));
    }
    uint32_t* ph = (uint32_t*)(Yb + (size_t)row * KA + col);
    uint32_t* pl = (uint32_t*)(Yb + (size_t)row * KA + D + col);
    ph[0] = hp[0]; ph[1] = hp[1];
    pl[0] = lp[0]; pl[1] = lp[1];
}

// ---------------------------------------------------------------------------
// bf16 mma.sync GEMM with hi/lo split (3 products).
// mode 0: fp32 out [m][n]   mode 1: bf16 hi/lo out to [B,H,S,128], scaled.
// ---------------------------------------------------------------------------
constexpr int BKC = 32;
constexpr int NCH = D / BKC;               // 32 chunks
constexpr int TILE_B  = 128 * BKC * 2;     // 8192 B per sub-tile
constexpr int STAGE_B = 4 * TILE_B;        // 32 KB
constexpr int GEMM_SMEM = 2 * STAGE_B;     // 64 KB

__global__ __launch_bounds__(256)
void gemm_tc(const __nv_bfloat16* __restrict__ Ab, const __nv_bfloat16* __restrict__ Wb,
             const float* __restrict__ bias, float* __restrict__ Yf,
             __nv_bfloat16* __restrict__ Yb, float scale, int mode)
{
    extern __shared__ char smem[];
    const uint32_t sbase = smem_u32(smem);
    const int tid  = threadIdx.x;
    const int wid  = tid >> 5;
    const int lane = tid & 31;
    const int m0 = blockIdx.y * 128;
    const int n0 = blockIdx.x * 128;
    const int wm = (wid >> 2) * 64;
    const int wn = (wid & 3) * 32;

    float acc[4][4][4];
#pragma unroll
    for (int mi = 0; mi < 4; mi++)
#pragma unroll
        for (int ni = 0; ni < 4; ni++)
#pragma unroll
            for (int r = 0; r < 4; r++) acc[mi][ni][r] = 0.f;

    const int lr = tid >> 1;
    const int lh = tid & 1;

    auto load_chunk = [&](int c) {
        const uint32_t stage = sbase + (uint32_t)(c & 1) * STAGE_B;
        const int kc = c * BKC;
        const int mg = lr >> 3, r8 = lr & 7;
        const __nv_bfloat16* ga = Ab + (size_t)(m0 + lr) * KA + kc;
        const __nv_bfloat16* gw = Wb + (size_t)(n0 + lr) * KA + kc;
#pragma unroll
        for (int j = 0; j < 2; j++) {
            const int kg = lh * 2 + j;
            const uint32_t so = (uint32_t)((kg * 16 + mg) * 128 + r8 * 16);
            cp16(stage + 0 * TILE_B + so, ga + kg * 8);
            cp16(stage + 1 * TILE_B + so, ga + D + kg * 8);
            cp16(stage + 2 * TILE_B + so, gw + kg * 8);
            cp16(stage + 3 * TILE_B + so, gw + D + kg * 8);
        }
        asm volatile("cp.async.commit_group;");
    };

    load_chunk(0);
    load_chunk(1);

    const int gA  = lane >> 3;
    const int rA  = lane & 7;
    const int la  = lane & 15;
    const int gB  = la >> 3;
    const int rB  = la & 7;

    for (int c = 0; c < NCH; c++) {
        if (c + 1 < NCH) asm volatile("cp.async.wait_group 1;" ::: "memory");
        else             asm volatile("cp.async.wait_group 0;" ::: "memory");
        __syncthreads();

        const uint32_t stage = sbase + (uint32_t)(c & 1) * STAGE_B;
        const uint32_t ahiB = stage;
        const uint32_t aloB = stage + TILE_B;
        const uint32_t whiB = stage + 2 * TILE_B;
        const uint32_t wloB = stage + 3 * TILE_B;

#pragma unroll
        for (int ks = 0; ks < 2; ks++) {
            const int kg0 = ks * 2;
            uint32_t ahi[4][4], alo[4][4], bhi[4][2], blo[4][2];
#pragma unroll
            for (int mi = 0; mi < 4; mi++) {
                const int mgB = (wm >> 3) + mi * 2 + (gA & 1);
                const int kgB = kg0 + (gA >> 1);
                const uint32_t off = (uint32_t)((kgB * 16 + mgB) * 128 + rA * 16);
                ldmatrix_x4(ahi[mi][0], ahi[mi][1], ahi[mi][2], ahi[mi][3], ahiB + off);
                ldmatrix_x4(alo[mi][0], alo[mi][1], alo[mi][2], alo[mi][3], aloB + off);
            }
#pragma unroll
            for (int ni = 0; ni < 4; ni++) {
                const int ng  = (wn >> 3) + ni;
                const int kgB = kg0 + gB;
                const uint32_t off = (uint32_t)((kgB * 16 + ng) * 128 + rB * 16);
                ldmatrix_x2(bhi[ni][0], bhi[ni][1], whiB + off);
                ldmatrix_x2(blo[ni][0], blo[ni][1], wloB + off);
            }
#pragma unroll
            for (int mi = 0; mi < 4; mi++)
#pragma unroll
                for (int ni = 0; ni < 4; ni++) {
                    mma_bf16(acc[mi][ni], ahi[mi], bhi[ni]);
                    mma_bf16(acc[mi][ni], ahi[mi], blo[ni]);
                    mma_bf16(acc[mi][ni], alo[mi], bhi[ni]);
                }
        }
        __syncthreads();
        if (c + 2 < NCH) load_chunk(c + 2);
    }

    // epilogue
#pragma unroll
    for (int mi = 0; mi < 4; mi++) {
#pragma unroll
        for (int ni = 0; ni < 4; ni++) {
            const int m = m0 + wm + mi * 16 + (lane >> 2);
            const int n = n0 + wn + ni * 8 + (lane & 3) * 2;
            const float b0 = __ldg(&bias[n]);
            const float b1 = __ldg(&bias[n + 1]);
            const float v00 = (acc[mi][ni][0] + b0) * scale;
            const float v01 = (acc[mi][ni][1] + b1) * scale;
            const float v10 = (acc[mi][ni][2] + b0) * scale;
            const float v11 = (acc[mi][ni][3] + b1) * scale;
            if (mode == 1) {
                const int h  = n >> 6;
                const int dk = n & (DK - 1);
#pragma unroll
                for (int rr = 0; rr < 2; rr++) {
                    const int mr = m + rr * 8;
                    const float p0 = rr ? v10 : v00;
                    const float p1 = rr ? v11 : v01;
                    const int bb = mr >> 11;
                    const int s  = mr & (S - 1);
                    __nv_bfloat16* base =
                        Yb + (((size_t)bb * H + h) * S + s) * 128 + dk;
                    const uint32_t hp = cvt2bf(p1, p0);
                    const uint32_t lp = cvt2bf(p1 - bf_hi(hp), p0 - bf_lo(hp));
                    *(uint32_t*)(base)      = hp;
                    *(uint32_t*)(base + 64) = lp;
                }
            } else {
                *(float2*)(Yf + (size_t)m * D + n)       = make_float2(v00, v01);
                *(float2*)(Yf + (size_t)(m + 8) * D + n) = make_float2(v10, v11);
            }
        }
    }
}

// ---------------------------------------------------------------------------
// Tensor-core flash attention (bf16 hi/lo split, 3 products each GEMM).
// CTA = 128 queries x one (b,h); 8 warps x 16 query rows; 64-key tiles,
// 2-stage cp.async pipeline. Q pre-scaled by 0.125 at projection.
// smem: Q 32KB + 2 x (K 16KB + V 16KB) = 96KB.
// ---------------------------------------------------------------------------
constexpr int ATQ = 128;
constexpr int ATK = 64;
constexpr int NKT = S / ATK;             // 32
constexpr int Q_SMEM = ATQ * 128 * 2;    // 32768
constexpr int K_SMEM = ATK * 128 * 2;    // 16384
constexpr int AT_STAGE = 2 * K_SMEM;     // 32768
constexpr int ATT_SMEM = Q_SMEM + 2 * AT_STAGE;  // 98304

__global__ __launch_bounds__(256)
void attn_mma(const __nv_bfloat16* __restrict__ Qb, const __nv_bfloat16* __restrict__ Kb,
              const __nv_bfloat16* __restrict__ Vb, const int* __restrict__ mask,
              float* __restrict__ ctx)
{
    extern __shared__ char smem[];
    const uint32_t sq  = smem_u32(smem);
    const uint32_t skv = sq + Q_SMEM;
    const int tid = threadIdx.x, wid = tid >> 5, lane = tid & 31;
    const int b = blockIdx.z, h = blockIdx.y;
    const int q0blk = blockIdx.x * ATQ;
    const size_t headoff = ((size_t)(b * H + h) * S) * 128;
    const __nv_bfloat16* Qg = Qb + headoff + (size_t)q0blk * 128;
    const __nv_bfloat16* Kg = Kb + headoff;
    const __nv_bfloat16* Vg = Vb + headoff;
    const int wm = wid * 16;

    auto load_kv = [&](int c) {
        const uint32_t st = skv + (uint32_t)(c & 1) * AT_STAGE;
        const int r = tid & 63, g = tid >> 6;
        const __nv_bfloat16* ks = Kg + (size_t)(c * ATK + r) * 128;
        const __nv_bfloat16* vs = Vg + (size_t)(c * ATK + r) * 128;
#pragma unroll
        for (int j = 0; j < 4; j++) {
            const int cg = g * 4 + j;   // 16 col-groups (8 bf16 each)
            const uint32_t so = (uint32_t)(((cg * 8 + (r >> 3)) * 8 + (r & 7)) * 16);
            cp16(st + so, ks + cg * 8);
            cp16(st + K_SMEM + so, vs + cg * 8);
        }
        asm volatile("cp.async.commit_group;");
    };

    // Q tile load (with stage-0 group)
    {
        const int r = tid & 127, half = tid >> 7;
        const __nv_bfloat16* src = Qg + (size_t)r * 128;
#pragma unroll
        for (int j = 0; j < 8; j++) {
            const int cg = half * 8 + j;
            const uint32_t so = (uint32_t)(((cg * 16 + (r >> 3)) * 8 + (r & 7)) * 16);
            cp16(sq + so, src + cg * 8);
        }
    }
    load_kv(0);          // commits Q + stage0
    load_kv(1);

    asm volatile("cp.async.wait_group 1;" ::: "memory");
    __syncthreads();

    const int gA = lane >> 3, rA = lane & 7;

    // Q A-frags (persistent)
    uint32_t qhi[4][4], qlo[4][4];
#pragma unroll
    for (int kk = 0; kk < 4; kk++) {
        const int rg = (wm >> 3) + (gA & 1);
        const int cgh = 2 * kk + (gA >> 1);
        ldmatrix_x4(qhi[kk][0], qhi[kk][1], qhi[kk][2], qhi[kk][3],
                    sq + (uint32_t)(((cgh * 16 + rg) * 8 + rA) * 16));
        ldmatrix_x4(qlo[kk][0], qlo[kk][1], qlo[kk][2], qlo[kk][3],
                    sq + (uint32_t)((((cgh + 8) * 16 + rg) * 8 + rA) * 16));
    }

    float o[8][4];
#pragma unroll
    for (int ng = 0; ng < 8; ng++)
#pragma unroll
        for (int r = 0; r < 4; r++) o[ng][r] = 0.f;
    float m0 = -1e30f, m1 = -1e30f, l0 = 0.f, l1 = 0.f;

    const int r0l = lane >> 2, c0l = (lane & 3) * 2;
    const int qg0 = q0blk + wm + r0l;
    const int* mr0 = mask + ((size_t)b * S + qg0) * S + c0l;
    const int* mr1 = mr0 + 8 * S;

    for (int c = 0; c < NKT; c++) {
        if (c < NKT - 1) asm volatile("cp.async.wait_group 1;" ::: "memory");
        else             asm volatile("cp.async.wait_group 0;" ::: "memory");
        __syncthreads();

        const uint32_t kb_ = skv + (uint32_t)(c & 1) * AT_STAGE;
        const uint32_t vb_ = kb_ + K_SMEM;

        // ---- scores: S = Qhi·Khi + Qhi·Klo + Qlo·Khi ----
        float sc[8][4];
#pragma unroll
        for (int ng = 0; ng < 8; ng++)
#pragma unroll
            for (int r = 0; r < 4; r++) sc[ng][r] = 0.f;

#pragma unroll
        for (int ng = 0; ng < 8; ng += 2) {
#pragma unroll
            for (int kk = 0; kk < 4; kk++) {
                uint32_t kh[4], kl[4];
                const int rg = ng + (gA >> 1);
                const int cg = 2 * kk + (gA & 1);
                ldmatrix_x4(kh[0], kh[1], kh[2], kh[3],
                            kb_ + (uint32_t)(((cg * 8 + rg) * 8 + rA) * 16));
                ldmatrix_x4(kl[0], kl[1], kl[2], kl[3],
                            kb_ + (uint32_t)((((cg + 8) * 8 + rg) * 8 + rA) * 16));
                mma_bf16(sc[ng],     qhi[kk], kh + 0);
                mma_bf16(sc[ng],     qhi[kk], kl + 0);
                mma_bf16(sc[ng],     qlo[kk], kh + 0);
                mma_bf16(sc[ng + 1], qhi[kk], kh + 2);
                mma_bf16(sc[ng + 1], qhi[kk], kl + 2);
                mma_bf16(sc[ng + 1], qlo[kk], kh + 2);
            }
        }

        // ---- mask ----
        const int koff = c * ATK;
#pragma unroll
        for (int ng = 0; ng < 8; ng++) {
            const int2 mA = *(const int2*)(mr0 + koff + ng * 8);
            const int2 mB = *(const int2*)(mr1 + koff + ng * 8);
            if (mA.x == 0) sc[ng][0] = -1e9f;
            if (mA.y == 0) sc[ng][1] = -1e9f;
            if (mB.x == 0) sc[ng][2] = -1e9f;
            if (mB.y == 0) sc[ng][3] = -1e9f;
        }

        // ---- online softmax ----
        float mx0 = sc[0][0], mx1 = sc[0][2];
#pragma unroll
        for (int ng = 0; ng < 8; ng++) {
            mx0 = fmaxf(mx0, fmaxf(sc[ng][0], sc[ng][1]));
            mx1 = fmaxf(mx1, fmaxf(sc[ng][2], sc[ng][3]));
        }
        mx0 = fmaxf(mx0, __shfl_xor_sync(0xffffffffu, mx0, 1));
        mx0 = fmaxf(mx0, __shfl_xor_sync(0xffffffffu, mx0, 2));
        mx1 = fmaxf(mx1, __shfl_xor_sync(0xffffffffu, mx1, 1));
        mx1 = fmaxf(mx1, __shfl_xor_sync(0xffffffffu, mx1, 2));

        const float mn0 = fmaxf(m0, mx0);
        const float mn1 = fmaxf(m1, mx1);
        const float cr0 = __expf(m0 - mn0);
        const float cr1 = __expf(m1 - mn1);
#pragma unroll
        for (int ng = 0; ng < 8; ng++) {
            o[ng][0] *= cr0; o[ng][1] *= cr0;
            o[ng][2] *= cr1; o[ng][3] *= cr1;
        }

        uint32_t phi[4][4], plo[4][4];
        float rs0 = 0.f, rs1 = 0.f;
#pragma unroll
        for (int kp = 0; kp < 4; kp++) {
            const float p00 = __expf(sc[2*kp][0]   - mn0);
            const float p01 = __expf(sc[2*kp][1]   - mn0);
            const float p10 = __expf(sc[2*kp][2]   - mn1);
            const float p11 = __expf(sc[2*kp][3]   - mn1);
            const float p20 = __expf(sc[2*kp+1][0] - mn0);
            const float p21 = __expf(sc[2*kp+1][1] - mn0);
            const float p30 = __expf(sc[2*kp+1][2] - mn1);
            const float p31 = __expf(sc[2*kp+1][3] - mn1);
            rs0 += (p00 + p01) + (p20 + p21);
            rs1 += (p10 + p11) + (p30 + p31);
            phi[kp][0] = cvt2bf(p01, p00);
            phi[kp][1] = cvt2bf(p11, p10);
            phi[kp][2] = cvt2bf(p21, p20);
            phi[kp][3] = cvt2bf(p31, p30);
            plo[kp][0] = cvt2bf(p01 - bf_hi(phi[kp][0]), p00 - bf_lo(phi[kp][0]));
            plo[kp][1] = cvt2bf(p11 - bf_hi(phi[kp][1]), p10 - bf_lo(phi[kp][1]));
            plo[kp][2] = cvt2bf(p21 - bf_hi(phi[kp][2]), p20 - bf_lo(phi[kp][2]));
            plo[kp][3] = cvt2bf(p31 - bf_hi(phi[kp][3]), p30 - bf_lo(phi[kp][3]));
        }
        rs0 += __shfl_xor_sync(0xffffffffu, rs0, 1);
        rs0 += __shfl_xor_sync(0xffffffffu, rs0, 2);
        rs1 += __shfl_xor_sync(0xffffffffu, rs1, 1);
        rs1 += __shfl_xor_sync(0xffffffffu, rs1, 2);
        l0 = l0 * cr0 + rs0;
        l1 = l1 * cr1 + rs1;
        m0 = mn0; m1 = mn1;

        // ---- O += P·V  (Phi·Vhi + Phi·Vlo + Plo·Vhi) ----
#pragma unroll
        for (int ng = 0; ng < 8; ng += 2) {
#pragma unroll
            for (int kp = 0; kp < 4; kp++) {
                uint32_t vh[4], vl[4];
                const int rg = 2 * kp + (gA & 1);
                const int cg = ng + (gA >> 1);
                ldmatrix_x4_t(vh[0], vh[1], vh[2], vh[3],
                              vb_ + (uint32_t)(((cg * 8 + rg) * 8 + rA) * 16));
                ldmatrix_x4_t(vl[0], vl[1], vl[2], vl[3],
                              vb_ + (uint32_t)((((cg + 8) * 8 + rg) * 8 + rA) * 16));
                mma_bf16(o[ng],     phi[kp], vh + 0);
                mma_bf16(o[ng],     phi[kp], vl + 0);
                mma_bf16(o[ng],     plo[kp], vh + 0);
                mma_bf16(o[ng + 1], phi[kp], vh + 2);
                mma_bf16(o[ng + 1], phi[kp], vl + 2);
                mma_bf16(o[ng + 1], plo[kp], vh + 2);
            }
        }

        __syncthreads();
        if (c + 2 < NKT) load_kv(c + 2);
    }

    // ---- write out ----
    const float inv0 = 1.f / l0;
    const float inv1 = 1.f / l1;
    float* dst0 = ctx + ((size_t)b * S + qg0) * D + h * DK + c0l;
    float* dst1 = dst0 + 8 * D;
#pragma unroll
    for (int ng = 0; ng < 8; ng++) {
        *(float2*)(dst0 + ng * 8) = make_float2(o[ng][0] * inv0, o[ng][1] * inv0);
        *(float2*)(dst1 + ng * 8) = make_float2(o[ng][2] * inv1, o[ng][3] * inv1);
    }
}

// ---------------------------------------------------------------------------
// launch
// ---------------------------------------------------------------------------
extern "C" void kernel_launch(void* const* d_in, const int* in_sizes, int n_in,
                              void* d_out, int out_size)
{
    const float* query = (const float*)d_in[0];
    const float* key_  = (const float*)d_in[1];
    const float* value = (const float*)d_in[2];
    const int*   amask = (const int*)  d_in[3];
    const float* w_q = (const float*)d_in[4];
    const float* b_q = (const float*)d_in[5];
    const float* w_k = (const float*)d_in[6];
    const float* b_k = (const float*)d_in[7];
    const float* w_v = (const float*)d_in[8];
    const float* b_v = (const float*)d_in[9];
    const float* w_o = (const float*)d_in[10];
    const float* b_o = (const float*)d_in[11];
    float* out = (float*)d_out;

    __nv_bfloat16 *gab, *gwb, *gqb, *gkb, *gvb;
    float *gctx;
    cudaGetSymbolAddress((void**)&gab,  g_ab);
    cudaGetSymbolAddress((void**)&gwb,  g_wb);
    cudaGetSymbolAddress((void**)&gqb,  g_qb);
    cudaGetSymbolAddress((void**)&gkb,  g_kb);
    cudaGetSymbolAddress((void**)&gvb,  g_vb);
    cudaGetSymbolAddress((void**)&gctx, g_ctx);

    cudaFuncSetAttribute(gemm_tc, cudaFuncAttributeMaxDynamicSharedMemorySize, GEMM_SMEM);
    cudaFuncSetAttribute(attn_mma, cudaFuncAttributeMaxDynamicSharedMemorySize, ATT_SMEM);

    const dim3 gg(D / 128, M_TOTAL / 128);
    const int ca_blocks = M_TOTAL * D / (4 * 256);  // 8192
    const int cw_blocks = D * D / (4 * 256);        // 1024

    conv_act<<<ca_blocks, 256>>>(query, gab);
    conv_act<<<cw_blocks, 256>>>(w_q, gwb);
    gemm_tc<<<gg, 256, GEMM_SMEM>>>(gab, gwb, b_q, nullptr, gqb, 0.125f, 1);

    conv_act<<<ca_blocks, 256>>>(key_, gab);
    conv_act<<<cw_blocks, 256>>>(w_k, gwb);
    gemm_tc<<<gg, 256, GEMM_SMEM>>>(gab, gwb, b_k, nullptr, gkb, 1.0f, 1);

    conv_act<<<ca_blocks, 256>>>(value, gab);
    conv_act<<<cw_blocks, 256>>>(w_v, gwb);
    gemm_tc<<<gg, 256, GEMM_SMEM>>>(gab, gwb, b_v, nullptr, gvb, 1.0f, 1);

    const dim3 ag(S / ATQ, H, B);   // (16, 16, 4)
    attn_mma<<<ag, 256, ATT_SMEM>>>(gqb, gkb, gvb, amask, gctx);

    conv_act<<<ca_blocks, 256>>>(gctx, gab);
    conv_act<<<cw_blocks, 256>>>(w_o, gwb);
    gemm_tc<<<gg, 256, GEMM_SMEM>>>(gab, gwb, b_o, out, nullptr, 1.0f, 0);
}

// round 6
// speedup vs baseline: 2.6468x; 1.0517x over previous
#include <cuda_runtime.h>
#include <cuda_bf16.h>
#include <cstdint>

// Problem constants
constexpr int B  = 4;
constexpr int S  = 2048;
constexpr int D  = 1024;
constexpr int H  = 16;
constexpr int DK = 64;
constexpr int M_TOTAL = B * S;   // 8192

constexpr int KA = 2 * D;        // 2048 (hi | lo)
constexpr size_t ACT_SLOT = (size_t)M_TOTAL * KA;   // elems per activation slot
constexpr size_t W_SLOT   = (size_t)D * KA;
constexpr size_t HEAD_SLOT = (size_t)B * H * S * 128;

// ---------------------------------------------------------------------------
// Device scratch (allocation-free rule)
// ---------------------------------------------------------------------------
__device__ __nv_bfloat16 g_ab3[3 * ACT_SLOT];    // 96 MB: q,k,v acts; slot0 reused for attn out
__device__ __nv_bfloat16 g_wb4[4 * W_SLOT];      // 16 MB: w_q,w_k,w_v,w_o
__device__ __nv_bfloat16 g_qkvb[3 * HEAD_SLOT];  // 96 MB: Q,K,V head-major hi/lo

// ---------------------------------------------------------------------------
// helpers
// ---------------------------------------------------------------------------
__device__ __forceinline__ uint32_t smem_u32(const void* p) {
    uint32_t a;
    asm("{ .reg .u64 t; cvta.to.shared.u64 t, %1; cvt.u32.u64 %0, t; }"
        : "=r"(a) : "l"(p));
    return a;
}
__device__ __forceinline__ void cp16(uint32_t s, const void* g) {
    asm volatile("cp.async.cg.shared.global [%0], [%1], 16;" :: "r"(s), "l"(g));
}
__device__ __forceinline__ void ldmatrix_x4(uint32_t& r0, uint32_t& r1,
                                            uint32_t& r2, uint32_t& r3, uint32_t a) {
    asm volatile("ldmatrix.sync.aligned.m8n8.x4.shared.b16 {%0,%1,%2,%3}, [%4];"
                 : "=r"(r0), "=r"(r1), "=r"(r2), "=r"(r3) : "r"(a));
}
__device__ __forceinline__ void ldmatrix_x4_t(uint32_t& r0, uint32_t& r1,
                                              uint32_t& r2, uint32_t& r3, uint32_t a) {
    asm volatile("ldmatrix.sync.aligned.m8n8.x4.trans.shared.b16 {%0,%1,%2,%3}, [%4];"
                 : "=r"(r0), "=r"(r1), "=r"(r2), "=r"(r3) : "r"(a));
}
__device__ __forceinline__ void mma_bf16(float* c, const uint32_t* a, const uint32_t* b) {
    asm volatile("mma.sync.aligned.m16n8k16.row.col.f32.bf16.bf16.f32 "
                 "{%0,%1,%2,%3},{%4,%5,%6,%7},{%8,%9},{%0,%1,%2,%3};"
                 : "+f"(c[0]), "+f"(c[1]), "+f"(c[2]), "+f"(c[3])
                 : "r"(a[0]), "r"(a[1]), "r"(a[2]), "r"(a[3]), "r"(b[0]), "r"(b[1]));
}
__device__ __forceinline__ uint32_t cvt2bf(float phi, float plo) {
    uint32_t r;
    asm("cvt.rn.bf16x2.f32 %0, %1, %2;" : "=r"(r) : "f"(phi), "f"(plo));
    return r;
}
__device__ __forceinline__ float bf_lo(uint32_t p) { return __uint_as_float(p << 16); }
__device__ __forceinline__ float bf_hi(uint32_t p) { return __uint_as_float(p & 0xFFFF0000u); }

// ---------------------------------------------------------------------------
// Conversion kernels: fp32 [R, D] -> bf16 hi/lo [R, 2D]
// ---------------------------------------------------------------------------
__device__ __forceinline__ void conv_body(const float* __restrict__ X,
                                          __nv_bfloat16* __restrict__ Yb)
{
    const int i = (blockIdx.x * 256 + threadIdx.x) * 4;
    float4 x = *(const float4*)(X + i);
    const int row = i >> 10;
    const int col = i & (D - 1);
    float xv[4] = {x.x, x.y, x.z, x.w};
    uint32_t hp[2], lp[2];
#pragma unroll
    for (int j = 0; j < 2; j++) {
        hp[j] = cvt2bf(xv[2*j+1], xv[2*j]);
        lp[j] = cvt2bf(xv[2*j+1] - bf_hi(hp[j]), xv[2*j] - bf_lo(hp[j]));
    }
    uint32_t* ph = (uint32_t*)(Yb + (size_t)row * KA + col);
    uint32_t* pl = (uint32_t*)(Yb + (size_t)row * KA + D + col);
    ph[0] = hp[0]; ph[1] = hp[1];
    pl[0] = lp[0]; pl[1] = lp[1];
}

__global__ __launch_bounds__(256)
void conv_acts(const float* __restrict__ q, const float* __restrict__ k,
               const float* __restrict__ v, __nv_bfloat16* __restrict__ Y3)
{
    const int z = blockIdx.y;
    const float* X = (z == 0) ? q : (z == 1) ? k : v;
    conv_body(X, Y3 + (size_t)z * ACT_SLOT);
}

__global__ __launch_bounds__(256)
void conv_ws(const float* __restrict__ wq, const float* __restrict__ wk,
             const float* __restrict__ wv, const float* __restrict__ wo,
             __nv_bfloat16* __restrict__ Y4)
{
    const int z = blockIdx.y;
    const float* X = (z == 0) ? wq : (z == 1) ? wk : (z == 2) ? wv : wo;
    conv_body(X, Y4 + (size_t)z * W_SLOT);
}

// ---------------------------------------------------------------------------
// bf16 mma.sync GEMM, hi/lo split (3 products), 3-stage cp.async pipeline,
// single barrier per chunk, loads issued before compute.
// grid (8, 64, Z). mode 1: bf16 hi/lo out to [B,H,S,128] (Q scaled 0.125).
// mode 0: fp32 out [m][n].
// ---------------------------------------------------------------------------
constexpr int BKC = 32;
constexpr int NCH = D / BKC;               // 32 chunks
constexpr int TILE_B  = 128 * BKC * 2;     // 8192 B per sub-tile
constexpr int STAGE_B = 4 * TILE_B;        // 32 KB
constexpr int GEMM_SMEM = 3 * STAGE_B;     // 96 KB

__global__ __launch_bounds__(256)
void gemm_tc(const __nv_bfloat16* __restrict__ Ab, const __nv_bfloat16* __restrict__ Wb,
             const float* __restrict__ bq, const float* __restrict__ bk,
             const float* __restrict__ bv,
             float* __restrict__ Yf, __nv_bfloat16* __restrict__ Yb, int mode)
{
    extern __shared__ char smem[];
    const uint32_t sbase = smem_u32(smem);
    const int tid  = threadIdx.x;
    const int wid  = tid >> 5;
    const int lane = tid & 31;
    const int z = blockIdx.z;
    const int m0 = blockIdx.y * 128;
    const int n0 = blockIdx.x * 128;
    const int wm = (wid >> 2) * 64;
    const int wn = (wid & 3) * 32;

    Ab += (size_t)z * ACT_SLOT;
    Wb += (size_t)z * W_SLOT;
    const float* bias = (z == 0) ? bq : (z == 1) ? bk : bv;
    const float scale = (mode == 1 && z == 0) ? 0.125f : 1.0f;
    __nv_bfloat16* Ybz = Yb + (size_t)z * HEAD_SLOT;

    float acc[4][4][4];
#pragma unroll
    for (int mi = 0; mi < 4; mi++)
#pragma unroll
        for (int ni = 0; ni < 4; ni++)
#pragma unroll
            for (int r = 0; r < 4; r++) acc[mi][ni][r] = 0.f;

    const int lr = tid >> 1;
    const int lh = tid & 1;

    auto load_chunk = [&](int c) {
        const uint32_t stage = sbase + (uint32_t)(c % 3) * STAGE_B;
        const int kc = c * BKC;
        const int mg = lr >> 3, r8 = lr & 7;
        const __nv_bfloat16* ga = Ab + (size_t)(m0 + lr) * KA + kc;
        const __nv_bfloat16* gw = Wb + (size_t)(n0 + lr) * KA + kc;
#pragma unroll
        for (int j = 0; j < 2; j++) {
            const int kg = lh * 2 + j;
            const uint32_t so = (uint32_t)((kg * 16 + mg) * 128 + r8 * 16);
            cp16(stage + 0 * TILE_B + so, ga + kg * 8);
            cp16(stage + 1 * TILE_B + so, ga + D + kg * 8);
            cp16(stage + 2 * TILE_B + so, gw + kg * 8);
            cp16(stage + 3 * TILE_B + so, gw + D + kg * 8);
        }
        asm volatile("cp.async.commit_group;");
    };

    load_chunk(0);
    load_chunk(1);

    const int gA = lane >> 3;
    const int rA = lane & 7;

    for (int c = 0; c < NCH; c++) {
        if (c + 1 < NCH) asm volatile("cp.async.wait_group 1;" ::: "memory");
        else             asm volatile("cp.async.wait_group 0;" ::: "memory");
        __syncthreads();
        if (c + 2 < NCH) load_chunk(c + 2);   // buffer consumed at iter c-1: safe

        const uint32_t stage = sbase + (uint32_t)(c % 3) * STAGE_B;
        const uint32_t ahiB = stage;
        const uint32_t aloB = stage + TILE_B;
        const uint32_t whiB = stage + 2 * TILE_B;
        const uint32_t wloB = stage + 3 * TILE_B;

#pragma unroll
        for (int ks = 0; ks < 2; ks++) {
            const int kg0 = ks * 2;
            uint32_t ahi[4][4], alo[4][4], bhi[4][2], blo[4][2];
#pragma unroll
            for (int mi = 0; mi < 4; mi++) {
                const int mgB = (wm >> 3) + mi * 2 + (gA & 1);
                const int kgB = kg0 + (gA >> 1);
                const uint32_t off = (uint32_t)((kgB * 16 + mgB) * 128 + rA * 16);
                ldmatrix_x4(ahi[mi][0], ahi[mi][1], ahi[mi][2], ahi[mi][3], ahiB + off);
                ldmatrix_x4(alo[mi][0], alo[mi][1], alo[mi][2], alo[mi][3], aloB + off);
            }
            // B: x4 loads batching (ni, ni+1) x (k-lo, k-hi)
#pragma unroll
            for (int np = 0; np < 2; np++) {
                const int ng  = (wn >> 3) + 2 * np + (gA >> 1);
                const int kgB = kg0 + (gA & 1);
                const uint32_t off = (uint32_t)((kgB * 16 + ng) * 128 + rA * 16);
                ldmatrix_x4(bhi[2*np][0], bhi[2*np][1], bhi[2*np+1][0], bhi[2*np+1][1],
                            whiB + off);
                ldmatrix_x4(blo[2*np][0], blo[2*np][1], blo[2*np+1][0], blo[2*np+1][1],
                            wloB + off);
            }
#pragma unroll
            for (int mi = 0; mi < 4; mi++)
#pragma unroll
                for (int ni = 0; ni < 4; ni++) {
                    mma_bf16(acc[mi][ni], ahi[mi], bhi[ni]);
                    mma_bf16(acc[mi][ni], ahi[mi], blo[ni]);
                    mma_bf16(acc[mi][ni], alo[mi], bhi[ni]);
                }
        }
    }

    // epilogue
#pragma unroll
    for (int mi = 0; mi < 4; mi++) {
#pragma unroll
        for (int ni = 0; ni < 4; ni++) {
            const int m = m0 + wm + mi * 16 + (lane >> 2);
            const int n = n0 + wn + ni * 8 + (lane & 3) * 2;
            const float b0 = __ldg(&bias[n]);
            const float b1 = __ldg(&bias[n + 1]);
            const float v00 = (acc[mi][ni][0] + b0) * scale;
            const float v01 = (acc[mi][ni][1] + b1) * scale;
            const float v10 = (acc[mi][ni][2] + b0) * scale;
            const float v11 = (acc[mi][ni][3] + b1) * scale;
            if (mode == 1) {
                const int h  = n >> 6;
                const int dk = n & (DK - 1);
#pragma unroll
                for (int rr = 0; rr < 2; rr++) {
                    const int mr = m + rr * 8;
                    const float p0 = rr ? v10 : v00;
                    const float p1 = rr ? v11 : v01;
                    const int bb = mr >> 11;
                    const int s  = mr & (S - 1);
                    __nv_bfloat16* base =
                        Ybz + (((size_t)bb * H + h) * S + s) * 128 + dk;
                    const uint32_t hp = cvt2bf(p1, p0);
                    const uint32_t lp = cvt2bf(p1 - bf_hi(hp), p0 - bf_lo(hp));
                    *(uint32_t*)(base)      = hp;
                    *(uint32_t*)(base + 64) = lp;
                }
            } else {
                *(float2*)(Yf + (size_t)m * D + n)       = make_float2(v00, v01);
                *(float2*)(Yf + (size_t)(m + 8) * D + n) = make_float2(v10, v11);
            }
        }
    }
}

// ---------------------------------------------------------------------------
// Tensor-core flash attention (bf16 hi/lo, 3 products each GEMM).
// 3-stage KV pipeline: stage 2 reuses the Q smem region (Q lives in registers
// after the fragment loads). One barrier per tile, loads before compute.
// Epilogue writes bf16 hi/lo directly into the O-projection's A buffer.
// ---------------------------------------------------------------------------
constexpr int ATQ = 128;
constexpr int ATK = 64;
constexpr int NKT = S / ATK;             // 32
constexpr int Q_SMEM = ATQ * 128 * 2;    // 32768
constexpr int K_SMEM = ATK * 128 * 2;    // 16384
constexpr int AT_STAGE = 2 * K_SMEM;     // 32768 (K + V)
constexpr int ATT_SMEM = Q_SMEM + 2 * AT_STAGE;  // 98304

__global__ __launch_bounds__(256)
void attn_mma(const __nv_bfloat16* __restrict__ QKV, const int* __restrict__ mask,
              __nv_bfloat16* __restrict__ Aout)
{
    extern __shared__ char smem[];
    const uint32_t sq  = smem_u32(smem);
    const uint32_t skv = sq + Q_SMEM;
    const int tid = threadIdx.x, wid = tid >> 5, lane = tid & 31;
    const int b = blockIdx.z, h = blockIdx.y;
    const int q0blk = blockIdx.x * ATQ;
    const size_t headoff = ((size_t)(b * H + h) * S) * 128;
    const __nv_bfloat16* Qg = QKV + headoff + (size_t)q0blk * 128;
    const __nv_bfloat16* Kg = QKV + HEAD_SLOT + headoff;
    const __nv_bfloat16* Vg = QKV + 2 * HEAD_SLOT + headoff;
    const int wm = wid * 16;

    auto stage_of = [&](int c) -> uint32_t {
        const int s3 = c % 3;
        return (s3 == 0) ? skv : (s3 == 1) ? (skv + AT_STAGE) : sq;
    };

    auto load_kv = [&](int c) {
        const uint32_t st = stage_of(c);
        const int r = tid & 63, g = tid >> 6;
        const __nv_bfloat16* ks = Kg + (size_t)(c * ATK + r) * 128;
        const __nv_bfloat16* vs = Vg + (size_t)(c * ATK + r) * 128;
#pragma unroll
        for (int j = 0; j < 4; j++) {
            const int cg = g * 4 + j;
            const uint32_t so = (uint32_t)(((cg * 8 + (r >> 3)) * 8 + (r & 7)) * 16);
            cp16(st + so, ks + cg * 8);
            cp16(st + K_SMEM + so, vs + cg * 8);
        }
        asm volatile("cp.async.commit_group;");
    };

    // Q tile load (grouped with stage-0 commit)
    {
        const int r = tid & 127, half = tid >> 7;
        const __nv_bfloat16* src = Qg + (size_t)r * 128;
#pragma unroll
        for (int j = 0; j < 8; j++) {
            const int cg = half * 8 + j;
            const uint32_t so = (uint32_t)(((cg * 16 + (r >> 3)) * 8 + (r & 7)) * 16);
            cp16(sq + so, src + cg * 8);
        }
    }
    load_kv(0);
    load_kv(1);

    asm volatile("cp.async.wait_group 1;" ::: "memory");
    __syncthreads();

    const int gA = lane >> 3, rA = lane & 7;

    // Q fragments -> registers (Q smem region becomes stage 2 afterwards)
    uint32_t qhi[4][4], qlo[4][4];
#pragma unroll
    for (int kk = 0; kk < 4; kk++) {
        const int rg = (wm >> 3) + (gA & 1);
        const int cgh = 2 * kk + (gA >> 1);
        ldmatrix_x4(qhi[kk][0], qhi[kk][1], qhi[kk][2], qhi[kk][3],
                    sq + (uint32_t)(((cgh * 16 + rg) * 8 + rA) * 16));
        ldmatrix_x4(qlo[kk][0], qlo[kk][1], qlo[kk][2], qlo[kk][3],
                    sq + (uint32_t)((((cgh + 8) * 16 + rg) * 8 + rA) * 16));
    }
    __syncthreads();   // all Q-frag reads done before sq is reused as stage 2

    float o[8][4];
#pragma unroll
    for (int ng = 0; ng < 8; ng++)
#pragma unroll
        for (int r = 0; r < 4; r++) o[ng][r] = 0.f;
    float m0 = -1e30f, m1 = -1e30f, l0 = 0.f, l1 = 0.f;

    const int r0l = lane >> 2, c0l = (lane & 3) * 2;
    const int qg0 = q0blk + wm + r0l;
    const int* mr0 = mask + ((size_t)b * S + qg0) * S + c0l;
    const int* mr1 = mr0 + 8 * S;

    for (int c = 0; c < NKT; c++) {
        if (c + 1 < NKT) asm volatile("cp.async.wait_group 1;" ::: "memory");
        else             asm volatile("cp.async.wait_group 0;" ::: "memory");
        __syncthreads();
        if (c + 2 < NKT) load_kv(c + 2);   // stage consumed at iter c-1: safe

        const uint32_t kb_ = stage_of(c);
        const uint32_t vb_ = kb_ + K_SMEM;

        // ---- scores ----
        float sc[8][4];
#pragma unroll
        for (int ng = 0; ng < 8; ng++)
#pragma unroll
            for (int r = 0; r < 4; r++) sc[ng][r] = 0.f;

#pragma unroll
        for (int ng = 0; ng < 8; ng += 2) {
#pragma unroll
            for (int kk = 0; kk < 4; kk++) {
                uint32_t kh[4], kl[4];
                const int rg = ng + (gA >> 1);
                const int cg = 2 * kk + (gA & 1);
                ldmatrix_x4(kh[0], kh[1], kh[2], kh[3],
                            kb_ + (uint32_t)(((cg * 8 + rg) * 8 + rA) * 16));
                ldmatrix_x4(kl[0], kl[1], kl[2], kl[3],
                            kb_ + (uint32_t)((((cg + 8) * 8 + rg) * 8 + rA) * 16));
                mma_bf16(sc[ng],     qhi[kk], kh + 0);
                mma_bf16(sc[ng],     qhi[kk], kl + 0);
                mma_bf16(sc[ng],     qlo[kk], kh + 0);
                mma_bf16(sc[ng + 1], qhi[kk], kh + 2);
                mma_bf16(sc[ng + 1], qhi[kk], kl + 2);
                mma_bf16(sc[ng + 1], qlo[kk], kh + 2);
            }
        }

        // ---- mask ----
        const int koff = c * ATK;
#pragma unroll
        for (int ng = 0; ng < 8; ng++) {
            const int2 mA = *(const int2*)(mr0 + koff + ng * 8);
            const int2 mB = *(const int2*)(mr1 + koff + ng * 8);
            if (mA.x == 0) sc[ng][0] = -1e9f;
            if (mA.y == 0) sc[ng][1] = -1e9f;
            if (mB.x == 0) sc[ng][2] = -1e9f;
            if (mB.y == 0) sc[ng][3] = -1e9f;
        }

        // ---- online softmax ----
        float mx0 = sc[0][0], mx1 = sc[0][2];
#pragma unroll
        for (int ng = 0; ng < 8; ng++) {
            mx0 = fmaxf(mx0, fmaxf(sc[ng][0], sc[ng][1]));
            mx1 = fmaxf(mx1, fmaxf(sc[ng][2], sc[ng][3]));
        }
        mx0 = fmaxf(mx0, __shfl_xor_sync(0xffffffffu, mx0, 1));
        mx0 = fmaxf(mx0, __shfl_xor_sync(0xffffffffu, mx0, 2));
        mx1 = fmaxf(mx1, __shfl_xor_sync(0xffffffffu, mx1, 1));
        mx1 = fmaxf(mx1, __shfl_xor_sync(0xffffffffu, mx1, 2));

        const float mn0 = fmaxf(m0, mx0);
        const float mn1 = fmaxf(m1, mx1);
        const float cr0 = __expf(m0 - mn0);
        const float cr1 = __expf(m1 - mn1);
#pragma unroll
        for (int ng = 0; ng < 8; ng++) {
            o[ng][0] *= cr0; o[ng][1] *= cr0;
            o[ng][2] *= cr1; o[ng][3] *= cr1;
        }

        uint32_t phi[4][4], plo[4][4];
        float rs0 = 0.f, rs1 = 0.f;
#pragma unroll
        for (int kp = 0; kp < 4; kp++) {
            const float p00 = __expf(sc[2*kp][0]   - mn0);
            const float p01 = __expf(sc[2*kp][1]   - mn0);
            const float p10 = __expf(sc[2*kp][2]   - mn1);
            const float p11 = __expf(sc[2*kp][3]   - mn1);
            const float p20 = __expf(sc[2*kp+1][0] - mn0);
            const float p21 = __expf(sc[2*kp+1][1] - mn0);
            const float p30 = __expf(sc[2*kp+1][2] - mn1);
            const float p31 = __expf(sc[2*kp+1][3] - mn1);
            rs0 += (p00 + p01) + (p20 + p21);
            rs1 += (p10 + p11) + (p30 + p31);
            phi[kp][0] = cvt2bf(p01, p00);
            phi[kp][1] = cvt2bf(p11, p10);
            phi[kp][2] = cvt2bf(p21, p20);
            phi[kp][3] = cvt2bf(p31, p30);
            plo[kp][0] = cvt2bf(p01 - bf_hi(phi[kp][0]), p00 - bf_lo(phi[kp][0]));
            plo[kp][1] = cvt2bf(p11 - bf_hi(phi[kp][1]), p10 - bf_lo(phi[kp][1]));
            plo[kp][2] = cvt2bf(p21 - bf_hi(phi[kp][2]), p20 - bf_lo(phi[kp][2]));
            plo[kp][3] = cvt2bf(p31 - bf_hi(phi[kp][3]), p30 - bf_lo(phi[kp][3]));
        }
        rs0 += __shfl_xor_sync(0xffffffffu, rs0, 1);
        rs0 += __shfl_xor_sync(0xffffffffu, rs0, 2);
        rs1 += __shfl_xor_sync(0xffffffffu, rs1, 1);
        rs1 += __shfl_xor_sync(0xffffffffu, rs1, 2);
        l0 = l0 * cr0 + rs0;
        l1 = l1 * cr1 + rs1;
        m0 = mn0; m1 = mn1;

        // ---- O += P·V ----
#pragma unroll
        for (int ng = 0; ng < 8; ng += 2) {
#pragma unroll
            for (int kp = 0; kp < 4; kp++) {
                uint32_t vh[4], vl[4];
                const int rg = 2 * kp + (gA & 1);
                const int cg = ng + (gA >> 1);
                ldmatrix_x4_t(vh[0], vh[1], vh[2], vh[3],
                              vb_ + (uint32_t)(((cg * 8 + rg) * 8 + rA) * 16));
                ldmatrix_x4_t(vl[0], vl[1], vl[2], vl[3],
                              vb_ + (uint32_t)((((cg + 8) * 8 + rg) * 8 + rA) * 16));
                mma_bf16(o[ng],     phi[kp], vh + 0);
                mma_bf16(o[ng],     phi[kp], vl + 0);
                mma_bf16(o[ng],     plo[kp], vh + 0);
                mma_bf16(o[ng + 1], phi[kp], vh + 2);
                mma_bf16(o[ng + 1], phi[kp], vl + 2);
                mma_bf16(o[ng + 1], plo[kp], vh + 2);
            }
        }
    }

    // ---- epilogue: write bf16 hi/lo straight into the O-proj A buffer ----
    const float inv0 = 1.f / l0;
    const float inv1 = 1.f / l1;
    __nv_bfloat16* dst0 = Aout + (size_t)(b * S + qg0) * KA + h * DK + c0l;
    __nv_bfloat16* dst1 = dst0 + (size_t)8 * KA;
#pragma unroll
    for (int ng = 0; ng < 8; ng++) {
        const float x0 = o[ng][0] * inv0, x1 = o[ng][1] * inv0;
        const float y0 = o[ng][2] * inv1, y1 = o[ng][3] * inv1;
        const uint32_t hx = cvt2bf(x1, x0);
        const uint32_t lx = cvt2bf(x1 - bf_hi(hx), x0 - bf_lo(hx));
        const uint32_t hy = cvt2bf(y1, y0);
        const uint32_t ly = cvt2bf(y1 - bf_hi(hy), y0 - bf_lo(hy));
        *(uint32_t*)(dst0 + ng * 8)     = hx;
        *(uint32_t*)(dst0 + D + ng * 8) = lx;
        *(uint32_t*)(dst1 + ng * 8)     = hy;
        *(uint32_t*)(dst1 + D + ng * 8) = ly;
    }
}

// ---------------------------------------------------------------------------
// launch
// ---------------------------------------------------------------------------
extern "C" void kernel_launch(void* const* d_in, const int* in_sizes, int n_in,
                              void* d_out, int out_size)
{
    const float* query = (const float*)d_in[0];
    const float* key_  = (const float*)d_in[1];
    const float* value = (const float*)d_in[2];
    const int*   amask = (const int*)  d_in[3];
    const float* w_q = (const float*)d_in[4];
    const float* b_q = (const float*)d_in[5];
    const float* w_k = (const float*)d_in[6];
    const float* b_k = (const float*)d_in[7];
    const float* w_v = (const float*)d_in[8];
    const float* b_v = (const float*)d_in[9];
    const float* w_o = (const float*)d_in[10];
    const float* b_o = (const float*)d_in[11];
    float* out = (float*)d_out;

    __nv_bfloat16 *gab3, *gwb4, *gqkvb;
    cudaGetSymbolAddress((void**)&gab3,  g_ab3);
    cudaGetSymbolAddress((void**)&gwb4,  g_wb4);
    cudaGetSymbolAddress((void**)&gqkvb, g_qkvb);

    cudaFuncSetAttribute(gemm_tc, cudaFuncAttributeMaxDynamicSharedMemorySize, GEMM_SMEM);
    cudaFuncSetAttribute(attn_mma, cudaFuncAttributeMaxDynamicSharedMemorySize, ATT_SMEM);

    // 1. convert activations (q,k,v) and all 4 weights
    conv_acts<<<dim3(M_TOTAL * D / (4 * 256), 3), 256>>>(query, key_, value, gab3);
    conv_ws  <<<dim3(D * D / (4 * 256), 4), 256>>>(w_q, w_k, w_v, w_o, gwb4);

    // 2. batched QKV projection (grid.z = 3)
    gemm_tc<<<dim3(D / 128, M_TOTAL / 128, 3), 256, GEMM_SMEM>>>(
        gab3, gwb4, b_q, b_k, b_v, nullptr, gqkvb, 1);

    // 3. flash attention -> writes O-proj A buffer (slot 0) directly
    attn_mma<<<dim3(S / ATQ, H, B), 256, ATT_SMEM>>>(gqkvb, amask, gab3);

    // 4. output projection
    gemm_tc<<<dim3(D / 128, M_TOTAL / 128, 1), 256, GEMM_SMEM>>>(
        gab3, gwb4 + 3 * W_SLOT, b_o, b_o, b_o, out, nullptr, 0);
}